// round 6
// baseline (speedup 1.0000x reference)
#include <cuda_runtime.h>
#include <math_constants.h>
#include <cstdint>

// Problem constants
#define NROWS 1048576
#define HDIM  128
#define NSEG  128
#define NEG_SLOPE 0.01f
#define LOG2E 1.4426950408889634f

// Tiling
#define ROWS_PER_WARP 128
#define ROWS_PER_ITER 8
#define NUM_STAGES (ROWS_PER_WARP / ROWS_PER_ITER)    // 16
#define PIPE_D 3
#define WARPS_PER_BLOCK 4
#define THREADS_PER_BLOCK (WARPS_PER_BLOCK * 32)      // 128
#define NUM_WARPS (NROWS / ROWS_PER_WARP)             // 8192
#define NUM_BLOCKS (NUM_WARPS / WARPS_PER_BLOCK)      // 2048

// Scratch (device globals — zero-initialized; kernel restores zeros at end)
__device__ float g_d[NSEG];
__device__ float g_acc[NSEG * HDIM];
__device__ int   g_done;

// ---------------------------------------------------------------------------
// cp.async helpers
// ---------------------------------------------------------------------------
__device__ __forceinline__ void cp16(unsigned int dst_smem, const float4* src) {
    asm volatile("cp.async.cg.shared.global [%0], [%1], 16;\n"
                 :: "r"(dst_smem), "l"(src));
}
#define CP_COMMIT()  asm volatile("cp.async.commit_group;\n" ::: "memory")
#define CP_WAIT2()   asm volatile("cp.async.wait_group 2;\n" ::: "memory")

// ---------------------------------------------------------------------------
// Warp-collective q_score for segment s (wq4 pre-scaled by LOG2E).
// ---------------------------------------------------------------------------
__device__ __forceinline__ float warp_qscore(const float4* __restrict__ aq4,
                                             float4 wq4, int s, int lane)
{
    float4 a = aq4[(size_t)s * (HDIM / 4) + lane];
    float p = fmaf(a.x, wq4.x, fmaf(a.y, wq4.y, fmaf(a.z, wq4.z, a.w * wq4.w)));
#pragma unroll
    for (int off = 16; off; off >>= 1)
        p += __shfl_xor_sync(0xffffffffu, p, off);
    return p;
}

// ---------------------------------------------------------------------------
// Process one batch of 8 rows. Lane l owns columns [4l, 4l+4).
// ---------------------------------------------------------------------------
__device__ __forceinline__ void process8(const float4 hv[ROWS_PER_ITER],
                                         float4& acc, float& d,
                                         float qsc, float4 w4, int lane)
{
    float p[8];
#pragma unroll
    for (int j = 0; j < 8; j++)
        p[j] = fmaf(hv[j].x, w4.x,
               fmaf(hv[j].y, w4.y,
               fmaf(hv[j].z, w4.z, hv[j].w * w4.w)));

    // Lane-group tree reduce (17 SHFL instead of 40)
    const bool h16 = (lane & 16) != 0;
    const bool h8  = (lane & 8)  != 0;
    const bool h4b = (lane & 4)  != 0;

    float a[4];
#pragma unroll
    for (int j = 0; j < 4; j++) {
        float send = h16 ? p[j]     : p[j + 4];
        float keep = h16 ? p[j + 4] : p[j];
        a[j] = keep + __shfl_xor_sync(0xffffffffu, send, 16);
    }
    float bb[2];
#pragma unroll
    for (int j = 0; j < 2; j++) {
        float send = h8 ? a[j]     : a[j + 2];
        float keep = h8 ? a[j + 2] : a[j];
        bb[j] = keep + __shfl_xor_sync(0xffffffffu, send, 8);
    }
    {
        float send = h4b ? bb[0] : bb[1];
        float keep = h4b ? bb[1] : bb[0];
        float c = keep + __shfl_xor_sync(0xffffffffu, send, 4);
        c += __shfl_xor_sync(0xffffffffu, c, 2);
        c += __shfl_xor_sync(0xffffffffu, c, 1);
        p[0] = c;   // lane 4j holds full sum for row j
    }

    float e[8];
#pragma unroll
    for (int j = 0; j < 8; j++) {
        float g = __shfl_sync(0xffffffffu, p[0], j * 4) + qsc;
        g = fmaxf(g, NEG_SLOPE * g);
        e[j] = exp2f(g);
    }

    d += ((e[0] + e[1]) + (e[2] + e[3])) + ((e[4] + e[5]) + (e[6] + e[7]));

#define WSUM_COMP(comp)                                            \
    do {                                                           \
        float s0 = fmaf(e[1], hv[1].comp, e[0] * hv[0].comp);      \
        float s1 = fmaf(e[3], hv[3].comp, e[2] * hv[2].comp);      \
        float s2 = fmaf(e[5], hv[5].comp, e[4] * hv[4].comp);      \
        float s3 = fmaf(e[7], hv[7].comp, e[6] * hv[6].comp);      \
        acc.comp += (s0 + s1) + (s2 + s3);                         \
    } while (0)
    WSUM_COMP(x); WSUM_COMP(y); WSUM_COMP(z); WSUM_COMP(w);
#undef WSUM_COMP
}

__device__ __forceinline__ void flush_atomic(int segid, float d, float4 acc,
                                             int lane)
{
    if (lane == 0) atomicAdd(&g_d[segid], d);
    float* dst = g_acc + (size_t)segid * HDIM + lane * 4;
    atomicAdd(dst + 0, acc.x);
    atomicAdd(dst + 1, acc.y);
    atomicAdd(dst + 2, acc.z);
    atomicAdd(dst + 3, acc.w);
}

// ---------------------------------------------------------------------------
// Fused kernel: cp.async-pipelined gate + segment softmax-sum + finalize.
// Per-warp smem ring: 3 stages x 8 rows x 512B = 12KB. 4 warps = 48KB static.
// ---------------------------------------------------------------------------
__global__ void __launch_bounds__(THREADS_PER_BLOCK)
fused_kernel(const float4* __restrict__ h4,
             const float4* __restrict__ aq4,
             const float*  __restrict__ w,
             const int*    __restrict__ seg,
             float* __restrict__ out)
{
    __shared__ float4 tiles[WARPS_PER_BLOCK][PIPE_D][ROWS_PER_ITER][32]; // 48KB

    const int lane = threadIdx.x & 31;
    const int wib  = threadIdx.x >> 5;
    const int warp_gid = blockIdx.x * WARPS_PER_BLOCK + wib;
    const int row0 = warp_gid * ROWS_PER_WARP;
    const size_t stride = HDIM / 4;   // float4 per row

    float4 w4 = reinterpret_cast<const float4*>(w)[lane];
    w4.x *= LOG2E; w4.y *= LOG2E; w4.z *= LOG2E; w4.w *= LOG2E;
    float4 wq4 = reinterpret_cast<const float4*>(w + HDIM)[lane];
    wq4.x *= LOG2E; wq4.y *= LOG2E; wq4.z *= LOG2E; wq4.w *= LOG2E;

    float4 acc = make_float4(0.f, 0.f, 0.f, 0.f);
    float d = 0.f;
    int cur = seg[row0];
    const int last = seg[row0 + ROWS_PER_WARP - 1];
    const float4* base = h4 + (size_t)row0 * stride + lane;

    if (cur == last) {
        // ---------------- FAST PATH: cp.async pipelined ----------------
        const float qsc = warp_qscore(aq4, wq4, cur, lane);

        // smem base address of this warp's ring (each lane's own 16B slot)
        const unsigned int tbase =
            (unsigned int)__cvta_generic_to_shared(&tiles[wib][0][0][lane]);
        // stage s, row j slot address: tbase + (s*8 + j) * 512
        // prologue: fill PIPE_D stages
#pragma unroll
        for (int s = 0; s < PIPE_D; s++) {
#pragma unroll
            for (int j = 0; j < ROWS_PER_ITER; j++)
                cp16(tbase + (unsigned int)(s * ROWS_PER_ITER + j) * 512u,
                     base + (size_t)(s * ROWS_PER_ITER + j) * stride);
            CP_COMMIT();
        }

        int slot = 0;
        for (int it = 0; it < NUM_STAGES; it++) {
            CP_WAIT2();   // stage `it` complete (each lane copied its own 16B)

            float4 hv[ROWS_PER_ITER];
            const unsigned int saddr =
                tbase + (unsigned int)(slot * ROWS_PER_ITER) * 512u;
#pragma unroll
            for (int j = 0; j < ROWS_PER_ITER; j++)
                hv[j] = tiles[wib][slot][j][lane];

            // refill same slot with stage it+PIPE_D (arrives long after LDS)
            const int ps = it + PIPE_D;
            if (ps < NUM_STAGES) {
#pragma unroll
                for (int j = 0; j < ROWS_PER_ITER; j++)
                    cp16(saddr + (unsigned int)j * 512u,
                         base + (size_t)(ps * ROWS_PER_ITER + j) * stride);
            }
            CP_COMMIT();  // commit every iter (possibly empty) to keep count

            process8(hv, acc, d, qsc, w4, lane);
            slot = (slot == PIPE_D - 1) ? 0 : slot + 1;
        }
        flush_atomic(cur, d, acc, lane);
    } else {
        // ---------------- SLOW PATH: boundary inside chunk ------------------
        float qsc = warp_qscore(aq4, wq4, cur, lane);
        for (int r = row0; r < row0 + ROWS_PER_WARP; r += ROWS_PER_ITER) {
            float4 hv[ROWS_PER_ITER];
#pragma unroll
            for (int j = 0; j < ROWS_PER_ITER; j++)
                hv[j] = __ldcs(base + (size_t)(r - row0 + j) * stride);

            int s8 = seg[r + (lane & 7)];

            float g[ROWS_PER_ITER];
#pragma unroll
            for (int j = 0; j < ROWS_PER_ITER; j++) {
                float p = fmaf(hv[j].x, w4.x,
                          fmaf(hv[j].y, w4.y,
                          fmaf(hv[j].z, w4.z, hv[j].w * w4.w)));
#pragma unroll
                for (int off = 16; off; off >>= 1)
                    p += __shfl_xor_sync(0xffffffffu, p, off);
                g[j] = p;
            }

#pragma unroll
            for (int j = 0; j < ROWS_PER_ITER; j++) {
                int s = __shfl_sync(0xffffffffu, s8, j);
                if (s != cur) {
                    flush_atomic(cur, d, acc, lane);
                    d = 0.f;
                    acc = make_float4(0.f, 0.f, 0.f, 0.f);
                    cur = s;
                    qsc = warp_qscore(aq4, wq4, s, lane);
                }
                float gate = g[j] + qsc;
                gate = fmaxf(gate, NEG_SLOPE * gate);
                float e = exp2f(gate);
                d += e;
                acc.x = fmaf(e, hv[j].x, acc.x);
                acc.y = fmaf(e, hv[j].y, acc.y);
                acc.z = fmaf(e, hv[j].z, acc.z);
                acc.w = fmaf(e, hv[j].w, acc.w);
            }
        }
        flush_atomic(cur, d, acc, lane);
    }

    // -------------------- last-block finalize + reset -----------------------
    __syncthreads();
    __threadfence();

    // reuse tile smem for finalize scratch
    float* sinv    = reinterpret_cast<float*>(&tiles[0][0][0][0]);
    int*   sticket = reinterpret_cast<int*>(sinv + NSEG);

    if (threadIdx.x == 0)
        *sticket = atomicAdd(&g_done, 1);
    __syncthreads();

    if (*sticket == (int)gridDim.x - 1) {
        __threadfence();
        const int t = threadIdx.x;
        float dv = __ldcg(&g_d[t]);
        sinv[t] = 1.f / fmaxf(dv, 1e-20f);
        g_d[t] = 0.f;
        __syncthreads();
#pragma unroll 4
        for (int b = 0; b < NSEG; b++) {
            size_t idx = (size_t)b * HDIM + t;
            out[idx] = __ldcg(&g_acc[idx]) * sinv[b];
            g_acc[idx] = 0.f;
        }
        __syncthreads();
        if (t == 0) g_done = 0;
    }
}

// ---------------------------------------------------------------------------
// Launch: inputs per metadata order: h, attention_query, w, segment_ids.
// ---------------------------------------------------------------------------
extern "C" void kernel_launch(void* const* d_in, const int* in_sizes, int n_in,
                              void* d_out, int out_size)
{
    const float* h   = (const float*)d_in[0];
    const float* aq  = (const float*)d_in[1];
    const float* w   = (const float*)d_in[2];
    const int*   seg = (const int*)d_in[3];
    float* out = (float*)d_out;

    fused_kernel<<<NUM_BLOCKS, THREADS_PER_BLOCK>>>(
        (const float4*)h, (const float4*)aq, w, seg, out);
}

// round 7
// speedup vs baseline: 1.1507x; 1.1507x over previous
#include <cuda_runtime.h>
#include <math_constants.h>
#include <cstdint>

// Problem constants
#define NROWS 1048576
#define HDIM  128
#define NSEG  128
#define NEG_SLOPE 0.01f
#define LOG2E 1.4426950408889634f

// Tiling
#define ROWS_PER_WARP 64
#define ROWS_PER_ITER 4
#define NUM_ITERS (ROWS_PER_WARP / ROWS_PER_ITER)     // 16
#define WARPS_PER_BLOCK 8
#define THREADS_PER_BLOCK (WARPS_PER_BLOCK * 32)      // 256
#define NUM_WARPS (NROWS / ROWS_PER_WARP)             // 16384
#define NUM_BLOCKS (NUM_WARPS / WARPS_PER_BLOCK)      // 2048

// Scratch (device globals — zero-initialized; kernel restores zeros at end)
__device__ float g_d[NSEG];
__device__ float g_acc[NSEG * HDIM];
__device__ int   g_done;

// ---------------------------------------------------------------------------
// Warp-collective q_score for segment s (wq4 pre-scaled by LOG2E).
// ---------------------------------------------------------------------------
__device__ __forceinline__ float warp_qscore(const float4* __restrict__ aq4,
                                             const float*  __restrict__ w,
                                             int s, int lane)
{
    float4 a  = aq4[(size_t)s * (HDIM / 4) + lane];
    float4 wq = reinterpret_cast<const float4*>(w + HDIM)[lane];
    float p = fmaf(a.x, wq.x, fmaf(a.y, wq.y, fmaf(a.z, wq.z, a.w * wq.w)));
#pragma unroll
    for (int off = 16; off; off >>= 1)
        p += __shfl_xor_sync(0xffffffffu, p, off);
    return p * LOG2E;
}

// ---------------------------------------------------------------------------
// 4-row warp reduce: p[j] = this lane's 4-col partial of row j.
// Returns via e[]: exp2(leakyrelu(rowsum + qsc)). 10 SHFL total.
// ---------------------------------------------------------------------------
__device__ __forceinline__ void gates4(const float p[4], float e[4],
                                       float qsc, int lane)
{
    const bool h16 = (lane & 16) != 0;
    const bool h8  = (lane & 8)  != 0;

    float a0, a1;
    {
        float send = h16 ? p[0] : p[2];
        float keep = h16 ? p[2] : p[0];
        a0 = keep + __shfl_xor_sync(0xffffffffu, send, 16);
        send = h16 ? p[1] : p[3];
        keep = h16 ? p[3] : p[1];
        a1 = keep + __shfl_xor_sync(0xffffffffu, send, 16);
    }
    float b;
    {
        float send = h8 ? a0 : a1;
        float keep = h8 ? a1 : a0;
        b = keep + __shfl_xor_sync(0xffffffffu, send, 8);
    }
    b += __shfl_xor_sync(0xffffffffu, b, 4);
    b += __shfl_xor_sync(0xffffffffu, b, 2);
    b += __shfl_xor_sync(0xffffffffu, b, 1);
    // row r = 2*h16 + h8 full sum now in every lane of its 8-lane group.
#pragma unroll
    for (int j = 0; j < 4; j++) {
        float g = __shfl_sync(0xffffffffu, b, j * 8) + qsc;
        g = fmaxf(g, NEG_SLOPE * g);
        e[j] = exp2f(g);
    }
}

// Process one 4-row batch (already-loaded hv) into (acc, d).
__device__ __forceinline__ void process4(const float4 hv[4],
                                         float4& acc, float& d,
                                         float qsc, float4 w4, int lane)
{
    float p[4];
#pragma unroll
    for (int j = 0; j < 4; j++)
        p[j] = fmaf(hv[j].x, w4.x,
               fmaf(hv[j].y, w4.y,
               fmaf(hv[j].z, w4.z, hv[j].w * w4.w)));

    float e[4];
    gates4(p, e, qsc, lane);

    d += (e[0] + e[1]) + (e[2] + e[3]);
#pragma unroll
    for (int j = 0; j < 4; j++) {
        acc.x = fmaf(e[j], hv[j].x, acc.x);
        acc.y = fmaf(e[j], hv[j].y, acc.y);
        acc.z = fmaf(e[j], hv[j].z, acc.z);
        acc.w = fmaf(e[j], hv[j].w, acc.w);
    }
}

__device__ __forceinline__ void flush_atomic(int segid, float d, float4 acc,
                                             int lane)
{
    if (lane == 0) atomicAdd(&g_d[segid], d);
    float* dst = g_acc + (size_t)segid * HDIM + lane * 4;
    atomicAdd(dst + 0, acc.x);
    atomicAdd(dst + 1, acc.y);
    atomicAdd(dst + 2, acc.z);
    atomicAdd(dst + 3, acc.w);
}

// ---------------------------------------------------------------------------
// Fused kernel: register-double-buffered gate + segment softmax-sum +
// last-block finalize. Tuned for 32 warps/SM (64-reg cap).
// ---------------------------------------------------------------------------
__global__ void __launch_bounds__(THREADS_PER_BLOCK, 4)
fused_kernel(const float4* __restrict__ h4,
             const float4* __restrict__ aq4,
             const float*  __restrict__ w,
             const int*    __restrict__ seg,
             float* __restrict__ out)
{
    const int lane = threadIdx.x & 31;
    const int warp_gid = blockIdx.x * WARPS_PER_BLOCK + (threadIdx.x >> 5);
    const int row0 = warp_gid * ROWS_PER_WARP;
    const int stride = HDIM / 4;      // float4 per row

    float4 w4 = reinterpret_cast<const float4*>(w)[lane];
    w4.x *= LOG2E; w4.y *= LOG2E; w4.z *= LOG2E; w4.w *= LOG2E;

    float4 acc = make_float4(0.f, 0.f, 0.f, 0.f);
    float d = 0.f;
    int cur = seg[row0];
    const int last = seg[row0 + ROWS_PER_WARP - 1];
    const float4* base = h4 + (size_t)row0 * stride + lane;

    if (cur == last) {
        // ---------------- FAST PATH: single segment in chunk ----------------
        const float qsc = warp_qscore(aq4, w, cur, lane);
        float4 A[4], B[4];

#pragma unroll
        for (int j = 0; j < 4; j++)
            A[j] = __ldcs(base + j * stride);

        for (int it = 0; it < NUM_ITERS; it += 2) {
#pragma unroll
            for (int j = 0; j < 4; j++)
                B[j] = __ldcs(base + (4 + j) * stride);

            process4(A, acc, d, qsc, w4, lane);

            if (it + 2 < NUM_ITERS) {
#pragma unroll
                for (int j = 0; j < 4; j++)
                    A[j] = __ldcs(base + (8 + j) * stride);
            }

            process4(B, acc, d, qsc, w4, lane);
            base += 8 * stride;
        }
        flush_atomic(cur, d, acc, lane);
    } else {
        // ---------------- SLOW PATH: boundary inside chunk ------------------
        float qsc = warp_qscore(aq4, w, cur, lane);
        for (int r = row0; r < row0 + ROWS_PER_WARP; r += ROWS_PER_ITER) {
            float4 hv[4];
#pragma unroll
            for (int j = 0; j < 4; j++)
                hv[j] = __ldcs(base + (r - row0 + j) * stride);

            int s4 = seg[r + (lane & 3)];

            float p[4];
#pragma unroll
            for (int j = 0; j < 4; j++)
                p[j] = fmaf(hv[j].x, w4.x,
                       fmaf(hv[j].y, w4.y,
                       fmaf(hv[j].z, w4.z, hv[j].w * w4.w)));

            float rs[4];
#pragma unroll
            for (int j = 0; j < 4; j++) {
                float v = p[j];
#pragma unroll
                for (int off = 16; off; off >>= 1)
                    v += __shfl_xor_sync(0xffffffffu, v, off);
                rs[j] = v;
            }

#pragma unroll
            for (int j = 0; j < 4; j++) {
                int s = __shfl_sync(0xffffffffu, s4, j);
                if (s != cur) {
                    flush_atomic(cur, d, acc, lane);
                    d = 0.f;
                    acc = make_float4(0.f, 0.f, 0.f, 0.f);
                    cur = s;
                    qsc = warp_qscore(aq4, w, s, lane);
                }
                float g = rs[j] + qsc;
                g = fmaxf(g, NEG_SLOPE * g);
                float e = exp2f(g);
                d += e;
                acc.x = fmaf(e, hv[j].x, acc.x);
                acc.y = fmaf(e, hv[j].y, acc.y);
                acc.z = fmaf(e, hv[j].z, acc.z);
                acc.w = fmaf(e, hv[j].w, acc.w);
            }
        }
        flush_atomic(cur, d, acc, lane);
    }

    // -------------------- last-block finalize + reset -----------------------
    __syncthreads();
    __threadfence();

    __shared__ float sinv[NSEG];
    __shared__ int   sticket;

    if (threadIdx.x == 0)
        sticket = atomicAdd(&g_done, 1);
    __syncthreads();

    if (sticket == (int)gridDim.x - 1) {
        __threadfence();
        const int t = threadIdx.x;
        if (t < NSEG) {
            float dv = __ldcg(&g_d[t]);
            sinv[t] = 1.f / fmaxf(dv, 1e-20f);
            g_d[t] = 0.f;
        }
        __syncthreads();
#pragma unroll 4
        for (int i = t; i < NSEG * HDIM; i += THREADS_PER_BLOCK) {
            out[i] = __ldcg(&g_acc[i]) * sinv[i >> 7];
            g_acc[i] = 0.f;
        }
        __syncthreads();
        if (t == 0) g_done = 0;
    }
}

// ---------------------------------------------------------------------------
// Launch: inputs per metadata order: h, attention_query, w, segment_ids.
// ---------------------------------------------------------------------------
extern "C" void kernel_launch(void* const* d_in, const int* in_sizes, int n_in,
                              void* d_out, int out_size)
{
    const float* h   = (const float*)d_in[0];
    const float* aq  = (const float*)d_in[1];
    const float* w   = (const float*)d_in[2];
    const int*   seg = (const int*)d_in[3];
    float* out = (float*)d_out;

    fused_kernel<<<NUM_BLOCKS, THREADS_PER_BLOCK>>>(
        (const float4*)h, (const float4*)aq, w, seg, out);
}